// round 1
// baseline (speedup 1.0000x reference)
#include <cuda_runtime.h>
#include <cuda_bf16.h>

#define MAXN 100000
#define MAXE 1600000

// Scratch (device globals — no allocation allowed)
__device__ float g_deg [MAXN];          // degree, then rsqrt(deg) in place
__device__ float g_h1  [MAXN * 128];    // x @ W1
__device__ float g_act1[MAXN * 128];    // relu(agg1 + selfloop + b1)
__device__ float g_h2  [MAXN * 64];     // act1 @ W2
__device__ float g_agg1[MAXN * 128];
__device__ float g_agg2[MAXN * 64];

// ---------------------------------------------------------------------------
// init: zero accumulators, set deg = 1 (self loop)
__global__ void init_kernel(int n) {
    int i = blockIdx.x * blockDim.x + threadIdx.x;
    int total = n * 128;
    if (i < total) g_agg1[i] = 0.0f;
    if (i < n * 64) g_agg2[i] = 0.0f;
    if (i < n)      g_deg[i]  = 1.0f;
}

__global__ void deg_kernel(const int* __restrict__ dst, int e) {
    int i = blockIdx.x * blockDim.x + threadIdx.x;
    if (i < e) atomicAdd(&g_deg[dst[i]], 1.0f);
}

__global__ void rsqrt_kernel(int n) {
    int i = blockIdx.x * blockDim.x + threadIdx.x;
    if (i < n) g_deg[i] = rsqrtf(g_deg[i]);
}

// ---------------------------------------------------------------------------
// Register-blocked fp32 GEMM: C[M,Nn] = A[M,K] @ B[K,Nn]
template<int BM, int BN, int BK, int TM, int TN>
__device__ __forceinline__ void sgemm_body(
    const float* __restrict__ A, const float* __restrict__ B,
    float* __restrict__ C, int M, int K, int Nn)
{
    constexpr int NT = (BM / TM) * (BN / TN);
    __shared__ float As[BM * BK];
    __shared__ float Bs[BK * BN];

    const int tid = threadIdx.x;
    const int tx  = tid % (BN / TN);
    const int ty  = tid / (BN / TN);
    const int row0 = blockIdx.x * BM;

    float acc[TM][TN];
#pragma unroll
    for (int i = 0; i < TM; i++)
#pragma unroll
        for (int j = 0; j < TN; j++) acc[i][j] = 0.0f;

    for (int k0 = 0; k0 < K; k0 += BK) {
#pragma unroll
        for (int i = tid * 4; i < BM * BK; i += NT * 4) {
            int r = i / BK, c = i % BK;
            float4 v = make_float4(0.f, 0.f, 0.f, 0.f);
            if (row0 + r < M)
                v = *(const float4*)&A[(long)(row0 + r) * K + k0 + c];
            *(float4*)&As[i] = v;
        }
#pragma unroll
        for (int i = tid * 4; i < BK * BN; i += NT * 4) {
            int r = i / BN, c = i % BN;
            *(float4*)&Bs[i] = *(const float4*)&B[(long)(k0 + r) * Nn + c];
        }
        __syncthreads();

#pragma unroll
        for (int k = 0; k < BK; k++) {
            float a[TM], b[TN];
#pragma unroll
            for (int i = 0; i < TM; i++) a[i] = As[(ty * TM + i) * BK + k];
#pragma unroll
            for (int j = 0; j < TN; j++) b[j] = Bs[k * BN + tx * TN + j];
#pragma unroll
            for (int i = 0; i < TM; i++)
#pragma unroll
                for (int j = 0; j < TN; j++) acc[i][j] += a[i] * b[j];
        }
        __syncthreads();
    }

#pragma unroll
    for (int i = 0; i < TM; i++) {
        int row = row0 + ty * TM + i;
        if (row < M) {
            float4 v = make_float4(acc[i][0], acc[i][1], acc[i][2], acc[i][3]);
            *(float4*)&C[(long)row * Nn + tx * TN] = v;
        }
    }
}

__global__ void gemm1_kernel(const float* __restrict__ A,
                             const float* __restrict__ B, int M) {
    sgemm_body<64, 128, 32, 8, 4>(A, B, g_h1, M, 128, 128);   // 256 threads
}
__global__ void gemm2_kernel(const float* __restrict__ B, int M) {
    sgemm_body<64, 64, 32, 8, 4>(g_act1, B, g_h2, M, 128, 64); // 128 threads
}

// ---------------------------------------------------------------------------
// Layer-1 edge aggregation: one warp per edge, 128 cols, float4 vector atomics
__global__ void agg_kernel_128(const int* __restrict__ src,
                               const int* __restrict__ dst, int e) {
    int w    = (blockIdx.x * blockDim.x + threadIdx.x) >> 5;
    int lane = threadIdx.x & 31;
    if (w >= e) return;
    int s = src[w], d = dst[w];
    float norm = g_deg[s] * g_deg[d];
    float4 v = *(const float4*)&g_h1[s * 128 + lane * 4];
    v.x *= norm; v.y *= norm; v.z *= norm; v.w *= norm;
    atomicAdd((float4*)&g_agg1[d * 128 + lane * 4], v);
}

// Layer-2 edge aggregation: 16 lanes per edge (64 cols)
__global__ void agg_kernel_64(const int* __restrict__ src,
                              const int* __restrict__ dst, int e) {
    int t    = blockIdx.x * blockDim.x + threadIdx.x;
    int edge = t >> 4;
    int lane = t & 15;
    if (edge >= e) return;
    int s = src[edge], d = dst[edge];
    float norm = g_deg[s] * g_deg[d];
    float4 v = *(const float4*)&g_h2[s * 64 + lane * 4];
    v.x *= norm; v.y *= norm; v.z *= norm; v.w *= norm;
    atomicAdd((float4*)&g_agg2[d * 64 + lane * 4], v);
}

// ---------------------------------------------------------------------------
// Epilogue 1: act1 = relu(agg1 + dinv^2 * h1 + b1)   (self-loop folded in)
__global__ void relu_bias_kernel(const float* __restrict__ b1, int n) {
    int i = blockIdx.x * blockDim.x + threadIdx.x;   // one float4 per thread
    if (i >= n * 32) return;
    int node = i >> 5;
    int c4   = i & 31;
    float di = g_deg[node];
    float d2 = di * di;
    float4 a = *(const float4*)&g_agg1[i * 4];
    float4 h = *(const float4*)&g_h1[i * 4];
    float4 b = *(const float4*)&b1[c4 * 4];
    float4 r;
    r.x = fmaxf(fmaf(d2, h.x, a.x) + b.x, 0.f);
    r.y = fmaxf(fmaf(d2, h.y, a.y) + b.y, 0.f);
    r.z = fmaxf(fmaf(d2, h.z, a.z) + b.z, 0.f);
    r.w = fmaxf(fmaf(d2, h.w, a.w) + b.w, 0.f);
    *(float4*)&g_act1[i * 4] = r;
}

// Epilogue 2: o = agg2 + dinv^2*h2 + b2; out = log_softmax(o) per 64-col row
__global__ void out_kernel(const float* __restrict__ b2,
                           float* __restrict__ out, int n) {
    int node = (blockIdx.x * blockDim.x + threadIdx.x) >> 5;
    int lane = threadIdx.x & 31;
    if (node >= n) return;
    float di = g_deg[node];
    float d2 = di * di;
    int base = node * 64;
    float v0 = fmaf(d2, g_h2[base + lane],      g_agg2[base + lane])      + b2[lane];
    float v1 = fmaf(d2, g_h2[base + lane + 32], g_agg2[base + lane + 32]) + b2[lane + 32];
    float m = fmaxf(v0, v1);
#pragma unroll
    for (int o = 16; o; o >>= 1) m = fmaxf(m, __shfl_xor_sync(0xFFFFFFFFu, m, o));
    float s = expf(v0 - m) + expf(v1 - m);
#pragma unroll
    for (int o = 16; o; o >>= 1) s += __shfl_xor_sync(0xFFFFFFFFu, s, o);
    float lse = m + logf(s);
    out[base + lane]      = v0 - lse;
    out[base + lane + 32] = v1 - lse;
}

// ---------------------------------------------------------------------------
extern "C" void kernel_launch(void* const* d_in, const int* in_sizes, int n_in,
                              void* d_out, int out_size) {
    const float* x  = (const float*)d_in[0];
    const int*   ei = (const int*)  d_in[1];
    const float* W1 = (const float*)d_in[2];
    const float* b1 = (const float*)d_in[3];
    const float* W2 = (const float*)d_in[4];
    const float* b2 = (const float*)d_in[5];
    float* out = (float*)d_out;

    const int n = in_sizes[0] / 128;
    const int e = in_sizes[1] / 2;
    const int* src = ei;
    const int* dst = ei + e;

    init_kernel <<<(n * 128 + 255) / 256, 256>>>(n);
    deg_kernel  <<<(e + 255) / 256, 256>>>(dst, e);
    rsqrt_kernel<<<(n + 255) / 256, 256>>>(n);

    gemm1_kernel<<<(n + 63) / 64, 256>>>(x, W1, n);

    agg_kernel_128<<<(e * 32 + 255) / 256, 256>>>(src, dst, e);
    relu_bias_kernel<<<(n * 32 + 255) / 256, 256>>>(b1, n);

    gemm2_kernel<<<(n + 63) / 64, 128>>>(W2, n);

    agg_kernel_64<<<(e * 16 + 255) / 256, 256>>>(src, dst, e);
    out_kernel<<<(n * 32 + 255) / 256, 256>>>(b2, out, n);
}

// round 2
// speedup vs baseline: 1.8070x; 1.8070x over previous
#include <cuda_runtime.h>
#include <cuda_bf16.h>

#define MAXN 100000
#define MAXE 1600000
#define SCAN_B 1024
#define MAXBLK ((MAXN + SCAN_B - 1) / SCAN_B)

// ---------------- device scratch (no allocation allowed) -------------------
__device__ int   g_cnt    [MAXN];        // in-degree (excl. self loop)
__device__ int   g_rowptr [MAXN];        // CSR row start
__device__ int   g_fillpos[MAXN];        // fill cursor (copy of rowptr)
__device__ int   g_bsum   [MAXBLK];      // scan block sums
__device__ int   g_csr    [MAXE];        // src indices grouped by dst
__device__ float g_dinv   [MAXN];        // rsqrt(deg)
__device__ float g_h1p    [MAXN * 128];  // dinv * (x @ W1)
__device__ float g_act1   [MAXN * 128];  // relu(layer-1 out)
__device__ float g_h2p    [MAXN * 64];   // dinv * (act1 @ W2)

// ---------------------------------------------------------------------------
__global__ void zero_cnt_kernel(int n) {
    int i = blockIdx.x * blockDim.x + threadIdx.x;
    if (i < n) g_cnt[i] = 0;
}

__global__ void count_kernel(const int* __restrict__ dst, int e) {
    int i = blockIdx.x * blockDim.x + threadIdx.x;
    if (i < e) atomicAdd(&g_cnt[dst[i]], 1);
}

// block-wise reduction of counts -> g_bsum
__global__ void scan1_kernel(int n) {
    __shared__ int sh[SCAN_B];
    int i = blockIdx.x * SCAN_B + threadIdx.x;
    sh[threadIdx.x] = (i < n) ? g_cnt[i] : 0;
    __syncthreads();
#pragma unroll
    for (int o = SCAN_B / 2; o; o >>= 1) {
        if (threadIdx.x < o) sh[threadIdx.x] += sh[threadIdx.x + o];
        __syncthreads();
    }
    if (threadIdx.x == 0) g_bsum[blockIdx.x] = sh[0];
}

// serial exclusive scan over <=98 block sums
__global__ void scan2_kernel(int nb) {
    if (threadIdx.x == 0) {
        int acc = 0;
        for (int i = 0; i < nb; i++) { int v = g_bsum[i]; g_bsum[i] = acc; acc += v; }
    }
}

// per-block Hillis-Steele, emit rowptr/fillpos/dinv
__global__ void scan3_kernel(int n) {
    __shared__ int sh[SCAN_B];
    int t = threadIdx.x;
    int i = blockIdx.x * SCAN_B + t;
    int v = (i < n) ? g_cnt[i] : 0;
    sh[t] = v;
    __syncthreads();
#pragma unroll
    for (int o = 1; o < SCAN_B; o <<= 1) {
        int add = (t >= o) ? sh[t - o] : 0;
        __syncthreads();
        sh[t] += add;
        __syncthreads();
    }
    if (i < n) {
        int start = g_bsum[blockIdx.x] + sh[t] - v;   // exclusive
        g_rowptr[i]  = start;
        g_fillpos[i] = start;
        g_dinv[i]    = rsqrtf((float)(v + 1));
    }
}

__global__ void fill_kernel(const int* __restrict__ src,
                            const int* __restrict__ dst, int e) {
    int i = blockIdx.x * blockDim.x + threadIdx.x;
    if (i < e) {
        int d = dst[i];
        int slot = atomicAdd(&g_fillpos[d], 1);
        g_csr[slot] = src[i];
    }
}

// ---------------------------------------------------------------------------
// SGEMM: C[M,Nn] = dinv[row] * (A[M,K] @ B[K,Nn]),  As stored K-major (transposed)
template<int BM, int BN, int BK, int TM, int TN>
__device__ __forceinline__ void sgemm_body(
    const float* __restrict__ A, const float* __restrict__ B,
    float* __restrict__ C, int M, int K, int Nn)
{
    constexpr int NT = (BM / TM) * (BN / TN);
    __shared__ float As[BK * BM];   // As[k][m]
    __shared__ float Bs[BK * BN];   // Bs[k][n]

    const int tid  = threadIdx.x;
    const int tx   = tid % (BN / TN);
    const int ty   = tid / (BN / TN);
    const int row0 = blockIdx.x * BM;

    float acc[TM][TN];
#pragma unroll
    for (int i = 0; i < TM; i++)
#pragma unroll
        for (int j = 0; j < TN; j++) acc[i][j] = 0.0f;

    for (int k0 = 0; k0 < K; k0 += BK) {
        // load A tile, transpose into As[k][m]
#pragma unroll
        for (int idx = tid; idx < BM * BK / 4; idx += NT) {
            int r  = idx / (BK / 4);
            int c4 = idx % (BK / 4);
            float4 v = make_float4(0.f, 0.f, 0.f, 0.f);
            if (row0 + r < M)
                v = *(const float4*)&A[(long)(row0 + r) * K + k0 + c4 * 4];
            As[(c4 * 4 + 0) * BM + r] = v.x;
            As[(c4 * 4 + 1) * BM + r] = v.y;
            As[(c4 * 4 + 2) * BM + r] = v.z;
            As[(c4 * 4 + 3) * BM + r] = v.w;
        }
        // load B tile
#pragma unroll
        for (int idx = tid; idx < BK * BN / 4; idx += NT) {
            int r  = idx / (BN / 4);
            int c4 = idx % (BN / 4);
            *(float4*)&Bs[r * BN + c4 * 4] =
                *(const float4*)&B[(long)(k0 + r) * Nn + c4 * 4];
        }
        __syncthreads();

#pragma unroll
        for (int k = 0; k < BK; k++) {
            float a[TM], b[TN];
#pragma unroll
            for (int i = 0; i < TM; i += 4)
                *(float4*)&a[i] = *(const float4*)&As[k * BM + ty * TM + i];
#pragma unroll
            for (int j = 0; j < TN; j += 4)
                *(float4*)&b[j] = *(const float4*)&Bs[k * BN + tx * TN + j];
#pragma unroll
            for (int i = 0; i < TM; i++)
#pragma unroll
                for (int j = 0; j < TN; j++) acc[i][j] += a[i] * b[j];
        }
        __syncthreads();
    }

#pragma unroll
    for (int i = 0; i < TM; i++) {
        int row = row0 + ty * TM + i;
        if (row < M) {
            float s = g_dinv[row];
#pragma unroll
            for (int j = 0; j < TN; j += 4) {
                float4 v = make_float4(acc[i][j] * s, acc[i][j + 1] * s,
                                       acc[i][j + 2] * s, acc[i][j + 3] * s);
                *(float4*)&C[(long)row * Nn + tx * TN + j] = v;
            }
        }
    }
}

__global__ void gemm1_kernel(const float* __restrict__ A,
                             const float* __restrict__ B, int M) {
    sgemm_body<128, 128, 32, 8, 8>(A, B, g_h1p, M, 128, 128);  // 256 thr
}
__global__ void gemm2_kernel(const float* __restrict__ B, int M) {
    sgemm_body<128, 64, 32, 8, 4>(g_act1, B, g_h2p, M, 128, 64); // 256 thr
}

// ---------------------------------------------------------------------------
// Layer-1 pull aggregation + self loop + bias + relu. One warp per dst node.
__global__ void agg1_kernel(const float* __restrict__ b1, int n) {
    int w    = (blockIdx.x * blockDim.x + threadIdx.x) >> 5;
    int lane = threadIdx.x & 31;
    if (w >= n) return;

    int start = g_rowptr[w];
    int cnt   = g_cnt[w];
    const float4* hp = (const float4*)g_h1p;

    float4 acc = make_float4(0.f, 0.f, 0.f, 0.f);
    int j = 0;
    for (; j + 4 <= cnt; j += 4) {
        int s0 = g_csr[start + j];
        int s1 = g_csr[start + j + 1];
        int s2 = g_csr[start + j + 2];
        int s3 = g_csr[start + j + 3];
        float4 v0 = hp[s0 * 32 + lane];
        float4 v1 = hp[s1 * 32 + lane];
        float4 v2 = hp[s2 * 32 + lane];
        float4 v3 = hp[s3 * 32 + lane];
        acc.x += v0.x + v1.x + v2.x + v3.x;
        acc.y += v0.y + v1.y + v2.y + v3.y;
        acc.z += v0.z + v1.z + v2.z + v3.z;
        acc.w += v0.w + v1.w + v2.w + v3.w;
    }
    for (; j < cnt; j++) {
        int s = g_csr[start + j];
        float4 v = hp[s * 32 + lane];
        acc.x += v.x; acc.y += v.y; acc.z += v.z; acc.w += v.w;
    }

    float4 self = hp[w * 32 + lane];
    float  di   = g_dinv[w];
    float4 bb   = ((const float4*)b1)[lane];
    float4 r;
    r.x = fmaxf(fmaf(di, acc.x + self.x, bb.x), 0.f);
    r.y = fmaxf(fmaf(di, acc.y + self.y, bb.y), 0.f);
    r.z = fmaxf(fmaf(di, acc.z + self.z, bb.z), 0.f);
    r.w = fmaxf(fmaf(di, acc.w + self.w, bb.w), 0.f);
    ((float4*)g_act1)[w * 32 + lane] = r;
}

// Layer-2 pull aggregation + self loop + bias + log_softmax. Warp per node.
__global__ void agg2_kernel(const float* __restrict__ b2,
                            float* __restrict__ out, int n) {
    int w    = (blockIdx.x * blockDim.x + threadIdx.x) >> 5;
    int lane = threadIdx.x & 31;
    if (w >= n) return;

    int start = g_rowptr[w];
    int cnt   = g_cnt[w];
    const float2* hp = (const float2*)g_h2p;

    float2 acc = make_float2(0.f, 0.f);
    int j = 0;
    for (; j + 4 <= cnt; j += 4) {
        int s0 = g_csr[start + j];
        int s1 = g_csr[start + j + 1];
        int s2 = g_csr[start + j + 2];
        int s3 = g_csr[start + j + 3];
        float2 v0 = hp[s0 * 32 + lane];
        float2 v1 = hp[s1 * 32 + lane];
        float2 v2 = hp[s2 * 32 + lane];
        float2 v3 = hp[s3 * 32 + lane];
        acc.x += v0.x + v1.x + v2.x + v3.x;
        acc.y += v0.y + v1.y + v2.y + v3.y;
    }
    for (; j < cnt; j++) {
        int s = g_csr[start + j];
        float2 v = hp[s * 32 + lane];
        acc.x += v.x; acc.y += v.y;
    }

    float2 self = hp[w * 32 + lane];
    float  di   = g_dinv[w];
    float2 bb   = ((const float2*)b2)[lane];
    float ox = fmaf(di, acc.x + self.x, bb.x);
    float oy = fmaf(di, acc.y + self.y, bb.y);

    float m = fmaxf(ox, oy);
#pragma unroll
    for (int o = 16; o; o >>= 1) m = fmaxf(m, __shfl_xor_sync(0xFFFFFFFFu, m, o));
    float s = __expf(ox - m) + __expf(oy - m);
#pragma unroll
    for (int o = 16; o; o >>= 1) s += __shfl_xor_sync(0xFFFFFFFFu, s, o);
    float lse = m + __logf(s);

    ((float2*)out)[w * 32 + lane] = make_float2(ox - lse, oy - lse);
}

// ---------------------------------------------------------------------------
extern "C" void kernel_launch(void* const* d_in, const int* in_sizes, int n_in,
                              void* d_out, int out_size) {
    const float* x  = (const float*)d_in[0];
    const int*   ei = (const int*)  d_in[1];
    const float* W1 = (const float*)d_in[2];
    const float* b1 = (const float*)d_in[3];
    const float* W2 = (const float*)d_in[4];
    const float* b2 = (const float*)d_in[5];
    float* out = (float*)d_out;

    const int n = in_sizes[0] / 128;
    const int e = in_sizes[1] / 2;
    const int* src = ei;
    const int* dst = ei + e;
    const int nb = (n + SCAN_B - 1) / SCAN_B;

    zero_cnt_kernel<<<(n + 255) / 256, 256>>>(n);
    count_kernel   <<<(e + 255) / 256, 256>>>(dst, e);
    scan1_kernel   <<<nb, SCAN_B>>>(n);
    scan2_kernel   <<<1, 32>>>(nb);
    scan3_kernel   <<<nb, SCAN_B>>>(n);
    fill_kernel    <<<(e + 255) / 256, 256>>>(src, dst, e);

    gemm1_kernel<<<(n + 127) / 128, 256>>>(x, W1, n);
    agg1_kernel <<<(n * 32 + 255) / 256, 256>>>(b1, n);
    gemm2_kernel<<<(n + 127) / 128, 256>>>(W2, n);
    agg2_kernel <<<(n * 32 + 255) / 256, 256>>>(b2, out, n);
}

// round 3
// speedup vs baseline: 2.6126x; 1.4458x over previous
#include <cuda_runtime.h>
#include <cuda_bf16.h>
#include <cstdint>

#define MAXN 100000
#define MAXE 1600000
#define SCAN_B 1024
#define MAXBLK ((MAXN + SCAN_B - 1) / SCAN_B)

// ---------------- device scratch (no allocation allowed) -------------------
__device__ int   g_cnt    [MAXN];
__device__ int   g_rowptr [MAXN];
__device__ int   g_fillpos[MAXN];
__device__ int   g_bsum   [MAXBLK];
__device__ int   g_csr    [MAXE];
__device__ float g_dinv   [MAXN];
__device__ float g_h1p    [MAXN * 128];  // dinv * (x @ W1)
__device__ float g_act1   [MAXN * 128];
__device__ float g_h2p    [MAXN * 64];   // dinv * (act1 @ W2)

// ---------------------------------------------------------------------------
__global__ void zero_cnt_kernel(int n) {
    int i = blockIdx.x * blockDim.x + threadIdx.x;
    if (i < n) g_cnt[i] = 0;
}

__global__ void count_kernel(const int* __restrict__ dst, int e) {
    int i = blockIdx.x * blockDim.x + threadIdx.x;
    if (i < e) atomicAdd(&g_cnt[dst[i]], 1);
}

__global__ void scan1_kernel(int n) {
    __shared__ int sh[SCAN_B];
    int i = blockIdx.x * SCAN_B + threadIdx.x;
    sh[threadIdx.x] = (i < n) ? g_cnt[i] : 0;
    __syncthreads();
#pragma unroll
    for (int o = SCAN_B / 2; o; o >>= 1) {
        if (threadIdx.x < o) sh[threadIdx.x] += sh[threadIdx.x + o];
        __syncthreads();
    }
    if (threadIdx.x == 0) g_bsum[blockIdx.x] = sh[0];
}

// parallel exclusive scan over <=128 block sums (one block)
__global__ void scan2_kernel(int nb) {
    __shared__ int sh[128];
    int t = threadIdx.x;
    int v = (t < nb) ? g_bsum[t] : 0;
    sh[t] = v;
    __syncthreads();
#pragma unroll
    for (int o = 1; o < 128; o <<= 1) {
        int add = (t >= o) ? sh[t - o] : 0;
        __syncthreads();
        sh[t] += add;
        __syncthreads();
    }
    if (t < nb) g_bsum[t] = sh[t] - v;   // exclusive
}

__global__ void scan3_kernel(int n) {
    __shared__ int sh[SCAN_B];
    int t = threadIdx.x;
    int i = blockIdx.x * SCAN_B + t;
    int v = (i < n) ? g_cnt[i] : 0;
    sh[t] = v;
    __syncthreads();
#pragma unroll
    for (int o = 1; o < SCAN_B; o <<= 1) {
        int add = (t >= o) ? sh[t - o] : 0;
        __syncthreads();
        sh[t] += add;
        __syncthreads();
    }
    if (i < n) {
        int start = g_bsum[blockIdx.x] + sh[t] - v;
        g_rowptr[i]  = start;
        g_fillpos[i] = start;
        g_dinv[i]    = rsqrtf((float)(v + 1));
    }
}

__global__ void fill_kernel(const int* __restrict__ src,
                            const int* __restrict__ dst, int e) {
    int i = blockIdx.x * blockDim.x + threadIdx.x;
    if (i < e) {
        int d = dst[i];
        int slot = atomicAdd(&g_fillpos[d], 1);
        g_csr[slot] = src[i];
    }
}

// ---------------------------------------------------------------------------
// tf32 tensor-core GEMM: C[M,BN] = dinv[row] * (A[M,128] @ B[128,BN])
// mma.sync.aligned.m16n8k8.row.col.f32.tf32.tf32.f32
__device__ __forceinline__ uint32_t f2tf32(float f) {
    uint32_t u;
    asm("cvt.rna.tf32.f32 %0, %1;" : "=r"(u) : "f"(f));
    return u;
}

__device__ __forceinline__ void mma_tf32(float c[4], const uint32_t a[4],
                                         uint32_t b0, uint32_t b1) {
    asm volatile(
        "mma.sync.aligned.m16n8k8.row.col.f32.tf32.tf32.f32 "
        "{%0,%1,%2,%3}, {%4,%5,%6,%7}, {%8,%9}, {%0,%1,%2,%3};"
        : "+f"(c[0]), "+f"(c[1]), "+f"(c[2]), "+f"(c[3])
        : "r"(a[0]), "r"(a[1]), "r"(a[2]), "r"(a[3]), "r"(b0), "r"(b1));
}

// BN: 128 or 64. MT: m16 tiles per warp. 256 threads / block, 128-row tiles.
template<int BN, int MT>
__device__ __forceinline__ void mma_gemm_body(
    const float* __restrict__ A, const float* __restrict__ B,
    float* __restrict__ C, int M)
{
    constexpr int WARPS_N  = BN / 64;     // 2 or 1
    constexpr int NT       = 8;           // n8 tiles per warp (64 cols)
    constexpr int AS       = 36;          // A smem stride (pad 4)
    constexpr int BS       = BN + 4;      // B smem stride
    __shared__ uint32_t As[128 * AS];
    __shared__ uint32_t Bs[32 * BS];

    const int tid  = threadIdx.x;
    const int wid  = tid >> 5;
    const int lane = tid & 31;
    const int wn   = (wid % WARPS_N) * 64;
    const int wm   = (wid / WARPS_N) * (MT * 16);
    const int row0 = blockIdx.x * 128;
    const int lg   = lane >> 2;   // group id (0..7)
    const int lt   = lane & 3;    // thread in group (0..3)

    float c[MT][NT][4];
#pragma unroll
    for (int mt = 0; mt < MT; mt++)
#pragma unroll
        for (int nt = 0; nt < NT; nt++)
#pragma unroll
            for (int q = 0; q < 4; q++) c[mt][nt][q] = 0.0f;

    for (int k0 = 0; k0 < 128; k0 += 32) {
        // A tile: 128 rows x 32 k  (1024 float4 slots)
#pragma unroll
        for (int i = 0; i < 4; i++) {
            int slot = tid + i * 256;
            int r = slot >> 3, k4 = slot & 7;
            float4 v = make_float4(0.f, 0.f, 0.f, 0.f);
            if (row0 + r < M)
                v = *(const float4*)&A[(long)(row0 + r) * 128 + k0 + k4 * 4];
            uint4 t = make_uint4(f2tf32(v.x), f2tf32(v.y), f2tf32(v.z), f2tf32(v.w));
            *(uint4*)&As[r * AS + k4 * 4] = t;
        }
        // B tile: 32 k x BN
#pragma unroll
        for (int i = 0; i < BN / 32; i++) {
            int slot = tid + i * 256;
            int k = slot / (BN / 4), n4 = slot % (BN / 4);
            float4 v = *(const float4*)&B[(long)(k0 + k) * BN + n4 * 4];
            uint4 t = make_uint4(f2tf32(v.x), f2tf32(v.y), f2tf32(v.z), f2tf32(v.w));
            *(uint4*)&Bs[k * BS + n4 * 4] = t;
        }
        __syncthreads();

#pragma unroll
        for (int ks = 0; ks < 4; ks++) {
            uint32_t a[MT][4];
            int ac = ks * 8 + lt;
#pragma unroll
            for (int mt = 0; mt < MT; mt++) {
                int r = wm + mt * 16 + lg;
                a[mt][0] = As[r * AS + ac];
                a[mt][1] = As[(r + 8) * AS + ac];
                a[mt][2] = As[r * AS + ac + 4];
                a[mt][3] = As[(r + 8) * AS + ac + 4];
            }
#pragma unroll
            for (int nt = 0; nt < NT; nt++) {
                int bc = wn + nt * 8 + lg;
                uint32_t b0 = Bs[(ks * 8 + lt) * BS + bc];
                uint32_t b1 = Bs[(ks * 8 + lt + 4) * BS + bc];
#pragma unroll
                for (int mt = 0; mt < MT; mt++)
                    mma_tf32(c[mt][nt], a[mt], b0, b1);
            }
        }
        __syncthreads();
    }

    // epilogue: scale by dinv[row], store
#pragma unroll
    for (int mt = 0; mt < MT; mt++) {
#pragma unroll
        for (int half = 0; half < 2; half++) {
            int r = row0 + wm + mt * 16 + lg + half * 8;
            if (r < M) {
                float s = g_dinv[r];
#pragma unroll
                for (int nt = 0; nt < NT; nt++) {
                    float2 v = make_float2(c[mt][nt][half * 2] * s,
                                           c[mt][nt][half * 2 + 1] * s);
                    *(float2*)&C[(long)r * BN + wn + nt * 8 + lt * 2] = v;
                }
            }
        }
    }
}

__global__ void gemm1_kernel(const float* __restrict__ A,
                             const float* __restrict__ B, int M) {
    mma_gemm_body<128, 2>(A, B, g_h1p, M);     // 8 warps: 4x2, warp 32x64
}
__global__ void gemm2_kernel(const float* __restrict__ B, int M) {
    mma_gemm_body<64, 1>(g_act1, B, g_h2p, M); // 8 warps: 8x1, warp 16x64
}

// ---------------------------------------------------------------------------
// Layer-1 pull aggregation + self loop + bias + relu. One warp per dst node.
__global__ void agg1_kernel(const float* __restrict__ b1, int n) {
    int w    = (blockIdx.x * blockDim.x + threadIdx.x) >> 5;
    int lane = threadIdx.x & 31;
    if (w >= n) return;

    int start = g_rowptr[w];
    int cnt   = g_cnt[w];
    const float4* hp = (const float4*)g_h1p;

    float4 acc = make_float4(0.f, 0.f, 0.f, 0.f);
    int j = 0;
    for (; j + 4 <= cnt; j += 4) {
        int s0 = g_csr[start + j];
        int s1 = g_csr[start + j + 1];
        int s2 = g_csr[start + j + 2];
        int s3 = g_csr[start + j + 3];
        float4 v0 = hp[s0 * 32 + lane];
        float4 v1 = hp[s1 * 32 + lane];
        float4 v2 = hp[s2 * 32 + lane];
        float4 v3 = hp[s3 * 32 + lane];
        acc.x += v0.x + v1.x + v2.x + v3.x;
        acc.y += v0.y + v1.y + v2.y + v3.y;
        acc.z += v0.z + v1.z + v2.z + v3.z;
        acc.w += v0.w + v1.w + v2.w + v3.w;
    }
    for (; j < cnt; j++) {
        int s = g_csr[start + j];
        float4 v = hp[s * 32 + lane];
        acc.x += v.x; acc.y += v.y; acc.z += v.z; acc.w += v.w;
    }

    float4 self = hp[w * 32 + lane];
    float  di   = g_dinv[w];
    float4 bb   = ((const float4*)b1)[lane];
    float4 r;
    r.x = fmaxf(fmaf(di, acc.x + self.x, bb.x), 0.f);
    r.y = fmaxf(fmaf(di, acc.y + self.y, bb.y), 0.f);
    r.z = fmaxf(fmaf(di, acc.z + self.z, bb.z), 0.f);
    r.w = fmaxf(fmaf(di, acc.w + self.w, bb.w), 0.f);
    ((float4*)g_act1)[w * 32 + lane] = r;
}

// Layer-2 pull aggregation + self loop + bias + log_softmax. Warp per node.
__global__ void agg2_kernel(const float* __restrict__ b2,
                            float* __restrict__ out, int n) {
    int w    = (blockIdx.x * blockDim.x + threadIdx.x) >> 5;
    int lane = threadIdx.x & 31;
    if (w >= n) return;

    int start = g_rowptr[w];
    int cnt   = g_cnt[w];
    const float2* hp = (const float2*)g_h2p;

    float2 acc = make_float2(0.f, 0.f);
    int j = 0;
    for (; j + 4 <= cnt; j += 4) {
        int s0 = g_csr[start + j];
        int s1 = g_csr[start + j + 1];
        int s2 = g_csr[start + j + 2];
        int s3 = g_csr[start + j + 3];
        float2 v0 = hp[s0 * 32 + lane];
        float2 v1 = hp[s1 * 32 + lane];
        float2 v2 = hp[s2 * 32 + lane];
        float2 v3 = hp[s3 * 32 + lane];
        acc.x += v0.x + v1.x + v2.x + v3.x;
        acc.y += v0.y + v1.y + v2.y + v3.y;
    }
    for (; j < cnt; j++) {
        int s = g_csr[start + j];
        float2 v = hp[s * 32 + lane];
        acc.x += v.x; acc.y += v.y;
    }

    float2 self = hp[w * 32 + lane];
    float  di   = g_dinv[w];
    float2 bb   = ((const float2*)b2)[lane];
    float ox = fmaf(di, acc.x + self.x, bb.x);
    float oy = fmaf(di, acc.y + self.y, bb.y);

    float m = fmaxf(ox, oy);
#pragma unroll
    for (int o = 16; o; o >>= 1) m = fmaxf(m, __shfl_xor_sync(0xFFFFFFFFu, m, o));
    float s = __expf(ox - m) + __expf(oy - m);
#pragma unroll
    for (int o = 16; o; o >>= 1) s += __shfl_xor_sync(0xFFFFFFFFu, s, o);
    float lse = m + __logf(s);

    ((float2*)out)[w * 32 + lane] = make_float2(ox - lse, oy - lse);
}

// ---------------------------------------------------------------------------
extern "C" void kernel_launch(void* const* d_in, const int* in_sizes, int n_in,
                              void* d_out, int out_size) {
    const float* x  = (const float*)d_in[0];
    const int*   ei = (const int*)  d_in[1];
    const float* W1 = (const float*)d_in[2];
    const float* b1 = (const float*)d_in[3];
    const float* W2 = (const float*)d_in[4];
    const float* b2 = (const float*)d_in[5];
    float* out = (float*)d_out;

    const int n = in_sizes[0] / 128;
    const int e = in_sizes[1] / 2;
    const int* src = ei;
    const int* dst = ei + e;
    const int nb = (n + SCAN_B - 1) / SCAN_B;

    zero_cnt_kernel<<<(n + 255) / 256, 256>>>(n);
    count_kernel   <<<(e + 255) / 256, 256>>>(dst, e);
    scan1_kernel   <<<nb, SCAN_B>>>(n);
    scan2_kernel   <<<1, 128>>>(nb);
    scan3_kernel   <<<nb, SCAN_B>>>(n);
    fill_kernel    <<<(e + 255) / 256, 256>>>(src, dst, e);

    gemm1_kernel<<<(n + 127) / 128, 256>>>(x, W1, n);
    agg1_kernel <<<(n * 32 + 255) / 256, 256>>>(b1, n);
    gemm2_kernel<<<(n + 127) / 128, 256>>>(W2, n);
    agg2_kernel <<<(n * 32 + 255) / 256, 256>>>(b2, out, n);
}